// round 8
// baseline (speedup 1.0000x reference)
#include <cuda_runtime.h>

#define B_TOTAL   131072
#define ROW_F     240
#define NBLOCKS   1024
#define NTHREADS  256
#define TPB       4                       // tiles per block
#define TROWS     32                      // rows per tile
#define FULL      0xFFFFFFFFu

#define PRED_TILE_F4   (TROWS * 60)       // 1920 float4 per tile
#define PRED_TILE_FLT  (TROWS * ROW_F)    // 7680 floats
#define INP_STRIDE     16                 // padded row stride (13 used)
#define INP_TILE_FLT   (TROWS * INP_STRIDE)
#define SMEM_BYTES     ((2 * PRED_TILE_FLT + 2 * INP_TILE_FLT) * 4)  // 65536

// deterministic two-stage reduction scratch (no allocation allowed)
__device__ double   g_partials[NBLOCKS * 2];
__device__ unsigned g_count = 0;

__device__ __forceinline__ float fsqrt_approx(float x) {
    float r; asm("sqrt.approx.f32 %0, %1;" : "=f"(r) : "f"(x)); return r;
}
__device__ __forceinline__ void cp_async16(unsigned s, const void* g) {
    asm volatile("cp.async.ca.shared.global [%0], [%1], 16;" :: "r"(s), "l"(g));
}
__device__ __forceinline__ void cp_async4(unsigned s, const void* g) {
    asm volatile("cp.async.ca.shared.global [%0], [%1], 4;" :: "r"(s), "l"(g));
}

__global__ __launch_bounds__(NTHREADS)
void constraint_loss_fused(const float* __restrict__ pred,
                           const float* __restrict__ tgt,
                           const float* __restrict__ inp,
                           float* __restrict__ out)
{
    extern __shared__ float smem[];
    float* s_pred = smem;                         // [2][7680]
    float* s_inp  = smem + 2 * PRED_TILE_FLT;     // [2][512]
    __shared__ double s_red[NTHREADS / 32][2];
    __shared__ bool   s_is_last;

    const int tid = threadIdx.x;
    const int row = tid >> 3;       // 0..31  (tile row)
    const int chk = tid & 7;        // 0..7   (timestep chunk)
    const int k0  = chk * 5;

    // ---- tile prefetch: whole pred tile + inp tile via cp.async ----
    auto prefetch = [&](int tile, int buf) {
        const int T = blockIdx.x * TPB + tile;
        const float4* src4 = (const float4*)pred + (size_t)T * PRED_TILE_F4;
        unsigned pb = (unsigned)__cvta_generic_to_shared(s_pred + buf * PRED_TILE_FLT);
        #pragma unroll
        for (int i = tid; i < PRED_TILE_F4; i += NTHREADS)
            cp_async16(pb + 16u * i, src4 + i);
        const float* isrc = inp + (size_t)T * TROWS * 13;
        unsigned ib = (unsigned)__cvta_generic_to_shared(s_inp + buf * INP_TILE_FLT);
        for (int i = tid; i < TROWS * 13; i += NTHREADS) {
            int ri = i / 13, f = i - ri * 13;
            cp_async4(ib + 4u * (ri * INP_STRIDE + f), isrc + i);
        }
        asm volatile("cp.async.commit_group;");
    };

    prefetch(0, 0);

    float mse_acc = 0.f, ob_acc = 0.f, dyn_acc = 0.f;

    #pragma unroll 1
    for (int t = 0; t < TPB; ++t) {
        const int buf = t & 1;
        if (t + 1 < TPB) {
            prefetch(t + 1, buf ^ 1);
            asm volatile("cp.async.wait_group 1;");
        } else {
            asm volatile("cp.async.wait_group 0;");
        }
        __syncthreads();

        const int T = blockIdx.x * TPB + t;
        const float* sp_t = s_pred + buf * PRED_TILE_FLT;
        const float* si_t = s_inp  + buf * INP_TILE_FLT;

        // ---- MSE phase: coalesced tgt LDG + coalesced pred LDS ----
        {
            const float4* t4  = (const float4*)tgt + (size_t)T * PRED_TILE_F4;
            const float4* p4s = (const float4*)sp_t;
            for (int i = tid; i < PRED_TILE_F4; i += NTHREADS) {
                float4 tv = t4[i];
                float4 pv = p4s[i];
                float d0 = pv.x - tv.x, d1 = pv.y - tv.y;
                float d2 = pv.z - tv.z, d3 = pv.w - tv.w;
                mse_acc += d0 * d0 + d1 * d1 + d2 * d2 + d3 * d3;
            }
        }

        // ---- dynamics phase: 1 thread = 1 row x 5 consecutive timesteps ----
        {
            const float* sr = sp_t + row * ROW_F;
            const float* ir = si_t + row * INP_STRIDE;
            float o0x = ir[4],  o0y = ir[5];
            float o1x = ir[7],  o1y = ir[8];
            float o2x = ir[10], o2y = ir[11];
            float q0 = ir[6] + 2.f, q1 = ir[9] + 2.f, q2 = ir[12] + 2.f;
            float rad0 = q0 * q0, rad1 = q1 * q1, rad2 = q2 * q2;

            float4 prev;
            if (chk == 0) prev = make_float4(ir[0], ir[1], ir[2], ir[3]);
            else          prev = *(const float4*)(sr + 4 * (k0 - 1));

            float r0 = 0.f, r1 = 0.f, r2 = 0.f, r3 = 0.f, obr = 0.f;
            #pragma unroll
            for (int i = 0; i < 5; ++i) {
                int k = k0 + i;
                float4 xk = *(const float4*)(sr + 4 * k);
                float2 uk = *(const float2*)(sr + 160 + 2 * k);
                float s, c; __sincosf(prev.z, &s, &c);
                r0 += xk.x - (prev.x + prev.w * c * 0.25f);
                r1 += xk.y - (prev.y + prev.w * s * 0.25f);
                r2 += xk.z - (prev.z + uk.y * 0.25f);
                r3 += xk.w - (prev.w + uk.x * 0.25f);
                float dx, dy;
                dx = xk.x - o0x; dy = xk.y - o0y;
                obr += fsqrt_approx(dx * dx + dy * dy) - rad0;
                dx = xk.x - o1x; dy = xk.y - o1y;
                obr += fsqrt_approx(dx * dx + dy * dy) - rad1;
                dx = xk.x - o2x; dy = xk.y - o2y;
                obr += fsqrt_approx(dx * dx + dy * dy) - rad2;
                prev = xk;
            }
            ob_acc += obr;

            // 8-lane segmented reduce of dyn residual 4-vector
            #pragma unroll
            for (int off = 4; off; off >>= 1) {
                r0 += __shfl_down_sync(FULL, r0, off, 8);
                r1 += __shfl_down_sync(FULL, r1, off, 8);
                r2 += __shfl_down_sync(FULL, r2, off, 8);
                r3 += __shfl_down_sync(FULL, r3, off, 8);
            }
            if (chk == 0)
                dyn_acc += fsqrt_approx(r0 * r0 + r1 * r1 + r2 * r2 + r3 * r3);
        }
        __syncthreads();   // tile fully consumed before its buffer is refilled
    }

    // ---- end-of-kernel reductions ----
    #pragma unroll
    for (int off = 16; off; off >>= 1) {
        mse_acc += __shfl_xor_sync(FULL, mse_acc, off);
        ob_acc  += __shfl_xor_sync(FULL, ob_acc,  off);
        dyn_acc += __shfl_xor_sync(FULL, dyn_acc, off);
    }
    if ((tid & 31) == 0) {
        s_red[tid >> 5][0] = (double)mse_acc;
        s_red[tid >> 5][1] = (double)ob_acc + (double)dyn_acc;
    }
    __syncthreads();
    if (tid == 0) {
        double m = 0.0, c = 0.0;
        #pragma unroll
        for (int w = 0; w < NTHREADS / 32; w++) { m += s_red[w][0]; c += s_red[w][1]; }
        g_partials[blockIdx.x * 2 + 0] = m;
        g_partials[blockIdx.x * 2 + 1] = c;
        __threadfence();
        unsigned ticket = atomicAdd(&g_count, 1u);
        s_is_last = (ticket == (unsigned)(NBLOCKS - 1));
    }
    __syncthreads();

    // ---- last block: deterministic fixed-order final sum ----
    if (s_is_last) {
        __threadfence();
        __shared__ double sm[NTHREADS];
        __shared__ double sc[NTHREADS];
        double m = 0.0, c = 0.0;
        for (int i = tid; i < NBLOCKS; i += NTHREADS) {
            m += g_partials[2 * i + 0];
            c += g_partials[2 * i + 1];
        }
        sm[tid] = m;
        sc[tid] = c;
        __syncthreads();
        for (int s = NTHREADS / 2; s > 0; s >>= 1) {
            if (tid < s) { sm[tid] += sm[tid + s]; sc[tid] += sc[tid + s]; }
            __syncthreads();
        }
        if (tid == 0) {
            double mse = sm[0] / ((double)B_TOTAL * (double)ROW_F);
            double con = sc[0] / (double)B_TOTAL;
            out[0] = (float)(mse + con);
            g_count = 0;      // reset for next graph replay
        }
    }
}

extern "C" void kernel_launch(void* const* d_in, const int* in_sizes, int n_in,
                              void* d_out, int out_size)
{
    const float* pred = (const float*)d_in[0];
    const float* tgt  = (const float*)d_in[1];
    const float* inp  = (const float*)d_in[2];
    float* out = (float*)d_out;

    cudaFuncSetAttribute(constraint_loss_fused,
                         cudaFuncAttributeMaxDynamicSharedMemorySize, SMEM_BYTES);
    constraint_loss_fused<<<NBLOCKS, NTHREADS, SMEM_BYTES>>>(pred, tgt, inp, out);
}